// round 10
// baseline (speedup 1.0000x reference)
#include <cuda_runtime.h>
#include <cuda_bf16.h>
#include <math.h>
#include <stdint.h>

// ---------------------------------------------------------------------------
// Problem constants
// ---------------------------------------------------------------------------
#define BATCH 4
#define SEQ   1024
#define DMODEL 512
#define DINNER 2048
#define NHEAD 8
#define DHEAD 64
#define NLAYER 6
#define NTOK (BATCH*SEQ)          // 4096
#define SQRT_D 22.627416997969522f
#define INV_SQRT_DH 0.125f

// ---------------------------------------------------------------------------
// Scratch (device globals: no allocations allowed)
// ---------------------------------------------------------------------------
__device__ float g_h   [NTOK*DMODEL];
__device__ float g_h1  [NTOK*DMODEL];
__device__ float g_ffn [NTOK*DMODEL];
__device__ float g_sk  [32u*1024u*1024u];   // SK[bh][i][j] = q_i . E[1023-i+j], j<=i

// bf16 split operand buffers
__device__ __nv_bfloat16 g_h_hi   [NTOK*DMODEL];
__device__ __nv_bfloat16 g_h_lo   [NTOK*DMODEL];
__device__ __nv_bfloat16 g_q_hi   [NTOK*DMODEL];
__device__ __nv_bfloat16 g_q_lo   [NTOK*DMODEL];
__device__ __nv_bfloat16 g_k_hi   [NTOK*DMODEL];
__device__ __nv_bfloat16 g_k_lo   [NTOK*DMODEL];
__device__ __nv_bfloat16 g_v_hi   [NTOK*DMODEL];
__device__ __nv_bfloat16 g_v_lo   [NTOK*DMODEL];
__device__ __nv_bfloat16 g_attn_hi[NTOK*DMODEL];
__device__ __nv_bfloat16 g_attn_lo[NTOK*DMODEL];
__device__ __nv_bfloat16 g_h1_hi  [NTOK*DMODEL];
__device__ __nv_bfloat16 g_h1_lo  [NTOK*DMODEL];
__device__ __nv_bfloat16 g_mid_hi [NTOK*DINNER];
__device__ __nv_bfloat16 g_mid_lo [NTOK*DINNER];
__device__ __nv_bfloat16 g_e_hi   [NLAYER*SEQ*DHEAD];
__device__ __nv_bfloat16 g_e_lo   [NLAYER*SEQ*DHEAD];

__device__ __nv_bfloat16 g_w4_hi[NLAYER*4*DMODEL*DMODEL];   // q,k,v,o transposed [N,K]
__device__ __nv_bfloat16 g_w4_lo[NLAYER*4*DMODEL*DMODEL];
__device__ __nv_bfloat16 g_w1_hi[NLAYER*DINNER*DMODEL];     // W1^T
__device__ __nv_bfloat16 g_w1_lo[NLAYER*DINNER*DMODEL];
__device__ __nv_bfloat16 g_w2_hi[NLAYER*DMODEL*DINNER];     // W2^T
__device__ __nv_bfloat16 g_w2_lo[NLAYER*DMODEL*DINNER];

// ---------------------------------------------------------------------------
// PTX helpers
// ---------------------------------------------------------------------------
__device__ __forceinline__ uint32_t smem_u32(const void* p) {
    uint32_t a;
    asm("{ .reg .u64 t; cvta.to.shared.u64 t, %1; cvt.u32.u64 %0, t; }" : "=r"(a) : "l"(p));
    return a;
}

__device__ __forceinline__ void cp_async16(uint32_t dst, const void* src) {
    asm volatile("cp.async.cg.shared.global [%0], [%1], 16;" :: "r"(dst), "l"(src));
}
#define CP_COMMIT() asm volatile("cp.async.commit_group;" ::: "memory")
#define CP_WAIT(N)  asm volatile("cp.async.wait_group %0;" :: "n"(N) : "memory")

__device__ __forceinline__ void ldm_x4(uint32_t& r0, uint32_t& r1, uint32_t& r2, uint32_t& r3,
                                       uint32_t addr) {
    asm volatile("ldmatrix.sync.aligned.m8n8.x4.shared.b16 {%0,%1,%2,%3}, [%4];"
                 : "=r"(r0), "=r"(r1), "=r"(r2), "=r"(r3) : "r"(addr));
}
__device__ __forceinline__ void ldm_x4t(uint32_t& r0, uint32_t& r1, uint32_t& r2, uint32_t& r3,
                                        uint32_t addr) {
    asm volatile("ldmatrix.sync.aligned.m8n8.x4.trans.shared.b16 {%0,%1,%2,%3}, [%4];"
                 : "=r"(r0), "=r"(r1), "=r"(r2), "=r"(r3) : "r"(addr));
}

__device__ __forceinline__ void mma_bf16(float& c0, float& c1, float& c2, float& c3,
                                         uint32_t a0, uint32_t a1, uint32_t a2, uint32_t a3,
                                         uint32_t b0, uint32_t b1) {
    asm volatile(
        "mma.sync.aligned.m16n8k16.row.col.f32.bf16.bf16.f32 "
        "{%0,%1,%2,%3}, {%4,%5,%6,%7}, {%8,%9}, {%0,%1,%2,%3};"
        : "+f"(c0), "+f"(c1), "+f"(c2), "+f"(c3)
        : "r"(a0), "r"(a1), "r"(a2), "r"(a3), "r"(b0), "r"(b1));
}

__device__ __forceinline__ void split_pack(float x, float y, uint32_t& hi, uint32_t& lo) {
    __nv_bfloat16 bx = __float2bfloat16(x), by = __float2bfloat16(y);
    hi = (uint32_t)__bfloat16_as_ushort(bx) | ((uint32_t)__bfloat16_as_ushort(by) << 16);
    __nv_bfloat16 rx = __float2bfloat16(x - __bfloat162float(bx));
    __nv_bfloat16 ry = __float2bfloat16(y - __bfloat162float(by));
    lo = (uint32_t)__bfloat16_as_ushort(rx) | ((uint32_t)__bfloat16_as_ushort(ry) << 16);
}

// ---------------------------------------------------------------------------
// Fused-split tensor-core GEMM: C = (Ahi+Alo)[M,K] @ (Bhi+Blo)^T[N,K] + bias
// BK=32, 2-stage cp.async pipeline (81920 B smem); __launch_bounds__(256,2)
// caps regs at 128 so 2 CTAs/SM actually materialize.
// CTA 128x128, 8 warps (2x4) of 64x32; 3 MMAs per fragment pair (hh, lh, hl).
// OMODE: 0 = fp32 out, 1 = bf16 hi/lo split out.
// ---------------------------------------------------------------------------
#define OPB 10240               // bytes per operand tile (128 rows * 80 B)
#define STG_BYTES (4*OPB)       // 40960
#define MMA_SMEM  (2*STG_BYTES) // 81920

template<int OMODE, bool RELU>
__device__ __forceinline__ void mma_gemm_body(
    const __nv_bfloat16* __restrict__ Ahi, const __nv_bfloat16* __restrict__ Alo,
    const __nv_bfloat16* __restrict__ Bhi, const __nv_bfloat16* __restrict__ Blo,
    const float* __restrict__ bias, float* __restrict__ C,
    __nv_bfloat16* __restrict__ Chi, __nv_bfloat16* __restrict__ Clo,
    int M, int N, int K)
{
    extern __shared__ char smem[];
    const uint32_t sb = smem_u32(smem);
    const int tid  = threadIdx.x;         // 256
    const int wid  = tid >> 5;
    const int lane = tid & 31;
    const int wm   = (wid & 1) * 64;
    const int wn   = (wid >> 1) * 32;
    const int m0 = blockIdx.y * 128;
    const int n0 = blockIdx.x * 128;

    const int S = K >> 5;                 // BK=32 stages

    float acc[4][4][4];
    #pragma unroll
    for (int i = 0; i < 4; i++)
        #pragma unroll
        for (int j = 0; j < 4; j++)
            #pragma unroll
            for (int e = 0; e < 4; e++) acc[i][j][e] = 0.f;

    auto load_stage = [&](int st) {
        const int k0 = st << 5;
        const uint32_t base = sb + (st & 1) * STG_BYTES;
        #pragma unroll
        for (int i = 0; i < 8; i++) {
            int idx = tid + i*256;                 // [0,2048)
            int op = idx >> 9;
            int rem = idx & 511;
            int r = rem >> 2, g = rem & 3;         // 4 x 16B chunks per 64B row
            uint32_t dst = base + op*OPB + r*80 + g*16;
            const __nv_bfloat16* src;
            if (op == 0)      src = Ahi + (size_t)(m0 + r)*K + k0 + g*8;
            else if (op == 1) src = Alo + (size_t)(m0 + r)*K + k0 + g*8;
            else if (op == 2) src = Bhi + (size_t)(n0 + r)*K + k0 + g*8;
            else              src = Blo + (size_t)(n0 + r)*K + k0 + g*8;
            cp_async16(dst, src);
        }
        CP_COMMIT();
    };

    load_stage(0);
    if (S > 1) load_stage(1);

    const int a_row = lane & 15;
    const int koff16 = (lane >> 4) * 16;

    for (int st = 0; st < S; ++st) {
        if (st + 1 < S) { CP_WAIT(1); }
        else            { CP_WAIT(0); }
        __syncthreads();

        const uint32_t base = sb + (st & 1) * STG_BYTES;

        #pragma unroll
        for (int ks = 0; ks < 2; ++ks) {
            uint32_t ah[4][4], al[4][4], bh[4][2], bl[4][2];
            #pragma unroll
            for (int mi = 0; mi < 4; ++mi) {
                uint32_t aa = base + (wm + mi*16 + a_row)*80 + ks*32 + koff16;
                ldm_x4(ah[mi][0], ah[mi][1], ah[mi][2], ah[mi][3], aa);
                ldm_x4(al[mi][0], al[mi][1], al[mi][2], al[mi][3], aa + OPB);
            }
            #pragma unroll
            for (int p = 0; p < 2; ++p) {
                uint32_t r0, r1, r2, r3;
                uint32_t ba = base + 2*OPB + (wn + p*16 + a_row)*80 + ks*32 + koff16;
                ldm_x4(r0, r1, r2, r3, ba);
                bh[2*p][0] = r0; bh[2*p][1] = r2; bh[2*p+1][0] = r1; bh[2*p+1][1] = r3;
                ldm_x4(r0, r1, r2, r3, ba + OPB);
                bl[2*p][0] = r0; bl[2*p][1] = r2; bl[2*p+1][0] = r1; bl[2*p+1][1] = r3;
            }
            #pragma unroll
            for (int mi = 0; mi < 4; ++mi)
                #pragma unroll
                for (int ni = 0; ni < 4; ++ni) {
                    mma_bf16(acc[mi][ni][0], acc[mi][ni][1], acc[mi][ni][2], acc[mi][ni][3],
                             ah[mi][0], ah[mi][1], ah[mi][2], ah[mi][3], bh[ni][0], bh[ni][1]);
                    mma_bf16(acc[mi][ni][0], acc[mi][ni][1], acc[mi][ni][2], acc[mi][ni][3],
                             al[mi][0], al[mi][1], al[mi][2], al[mi][3], bh[ni][0], bh[ni][1]);
                    mma_bf16(acc[mi][ni][0], acc[mi][ni][1], acc[mi][ni][2], acc[mi][ni][3],
                             ah[mi][0], ah[mi][1], ah[mi][2], ah[mi][3], bl[ni][0], bl[ni][1]);
                }
        }
        __syncthreads();
        if (st + 2 < S) load_stage(st + 2);
    }

    const int tg = lane >> 2;
    const int tc = (lane & 3) * 2;
    #pragma unroll
    for (int ni = 0; ni < 4; ++ni) {
        const int col = n0 + wn + ni*8 + tc;
        const float bz0 = bias[col], bz1 = bias[col + 1];
        #pragma unroll
        for (int mi = 0; mi < 4; ++mi) {
            const int row = m0 + wm + mi*16 + tg;
            float v0 = acc[mi][ni][0] + bz0, v1 = acc[mi][ni][1] + bz1;
            float v2 = acc[mi][ni][2] + bz0, v3 = acc[mi][ni][3] + bz1;
            if (RELU) {
                v0 = fmaxf(v0, 0.f); v1 = fmaxf(v1, 0.f);
                v2 = fmaxf(v2, 0.f); v3 = fmaxf(v3, 0.f);
            }
            if (OMODE == 0) {
                *reinterpret_cast<float2*>(C + (size_t)row*N + col) = make_float2(v0, v1);
                *reinterpret_cast<float2*>(C + (size_t)(row + 8)*N + col) = make_float2(v2, v3);
            } else {
                uint32_t h0, l0, h1, l1;
                split_pack(v0, v1, h0, l0);
                split_pack(v2, v3, h1, l1);
                *reinterpret_cast<uint32_t*>(Chi + (size_t)row*N + col) = h0;
                *reinterpret_cast<uint32_t*>(Clo + (size_t)row*N + col) = l0;
                *reinterpret_cast<uint32_t*>(Chi + (size_t)(row + 8)*N + col) = h1;
                *reinterpret_cast<uint32_t*>(Clo + (size_t)(row + 8)*N + col) = l1;
            }
        }
    }
}

template<int OMODE, bool RELU>
__global__ void __launch_bounds__(256, 2) mma_gemm_kernel(
    const __nv_bfloat16* __restrict__ Ahi, const __nv_bfloat16* __restrict__ Alo,
    const __nv_bfloat16* __restrict__ Bhi, const __nv_bfloat16* __restrict__ Blo,
    const float* __restrict__ bias, float* __restrict__ C,
    __nv_bfloat16* __restrict__ Chi, __nv_bfloat16* __restrict__ Clo,
    int M, int N, int K)
{
    mma_gemm_body<OMODE, RELU>(Ahi, Alo, Bhi, Blo, bias, C, Chi, Clo, M, N, K);
}

// QKV fused: split bf16 outputs for q,k,v
__global__ void __launch_bounds__(256, 2) mma_gemm_qkv_kernel(
    const __nv_bfloat16* __restrict__ Ahi, const __nv_bfloat16* __restrict__ Alo,
    const __nv_bfloat16* __restrict__ Whi, const __nv_bfloat16* __restrict__ Wlo,
    const float* __restrict__ bq, const float* __restrict__ bk, const float* __restrict__ bv,
    __nv_bfloat16* __restrict__ qh, __nv_bfloat16* __restrict__ ql,
    __nv_bfloat16* __restrict__ kh, __nv_bfloat16* __restrict__ kl,
    __nv_bfloat16* __restrict__ vh, __nv_bfloat16* __restrict__ vl)
{
    const int z = blockIdx.z;
    const size_t woff = (size_t)z * DMODEL * DMODEL;
    const float* bias = (z == 0) ? bq : (z == 1) ? bk : bv;
    __nv_bfloat16* Chi = (z == 0) ? qh : (z == 1) ? kh : vh;
    __nv_bfloat16* Clo = (z == 0) ? ql : (z == 1) ? kl : vl;
    mma_gemm_body<1, false>(Ahi, Alo, Whi + woff, Wlo + woff, bias, nullptr,
                            Chi, Clo, NTOK, DMODEL, DMODEL);
}

// ---------------------------------------------------------------------------
// Weight transpose + split: W[K,N] fp32 -> Whi/Wlo[N,K] bf16. z = layer.
// ---------------------------------------------------------------------------
__global__ void wconv_t_kernel(const float* __restrict__ W, __nv_bfloat16* __restrict__ Whi,
                               __nv_bfloat16* __restrict__ Wlo, int K, int N,
                               size_t strideW, size_t strideO) {
    __shared__ float t[32][33];
    const int l = blockIdx.z;
    W += (size_t)l * strideW; Whi += (size_t)l * strideO; Wlo += (size_t)l * strideO;
    const int tx = threadIdx.x & 31, ty = threadIdx.x >> 5;
    const int kb = blockIdx.y * 32, nb = blockIdx.x * 32;
    #pragma unroll
    for (int i = ty; i < 32; i += 8)
        t[i][tx] = W[(size_t)(kb + i)*N + nb + tx];
    __syncthreads();
    #pragma unroll
    for (int i = ty; i < 32; i += 8) {
        float x = t[tx][i];
        __nv_bfloat16 h = __float2bfloat16(x);
        __nv_bfloat16 lo = __float2bfloat16(x - __bfloat162float(h));
        size_t o = (size_t)(nb + i)*K + kb + tx;
        Whi[o] = h; Wlo[o] = lo;
    }
}

// E split (all layers): fp32 -> hi/lo bf16
__global__ void econv_kernel(const float* __restrict__ E) {
    int i4 = blockIdx.x * blockDim.x + threadIdx.x;   // [0, L*SEQ*DHEAD/4)
    float4 x = reinterpret_cast<const float4*>(E)[i4];
    uint32_t h0, l0, h1, l1;
    split_pack(x.x, x.y, h0, l0);
    split_pack(x.z, x.w, h1, l1);
    reinterpret_cast<uint2*>(g_e_hi)[i4] = make_uint2(h0, h1);
    reinterpret_cast<uint2*>(g_e_lo)[i4] = make_uint2(l0, l1);
}

// ---------------------------------------------------------------------------
// Embedding: h = emb[x]*sqrt(D) + pos; also emit bf16 hi/lo split.
// ---------------------------------------------------------------------------
__global__ void embed_kernel(const int* __restrict__ x, const float* __restrict__ emb,
                             const float* __restrict__ pos) {
    int i4 = blockIdx.x * blockDim.x + threadIdx.x;
    int idx = i4 * 4;
    int t = idx >> 9;
    int d = idx & 511;
    int s = t & (SEQ-1);
    int tok = x[t];
    float4 e = *reinterpret_cast<const float4*>(&emb[(size_t)tok*DMODEL + d]);
    float4 p = *reinterpret_cast<const float4*>(&pos[(size_t)s*DMODEL + d]);
    float4 hv = make_float4(e.x*SQRT_D + p.x, e.y*SQRT_D + p.y,
                            e.z*SQRT_D + p.z, e.w*SQRT_D + p.w);
    *reinterpret_cast<float4*>(&g_h[idx]) = hv;
    uint32_t h0, l0, h1, l1;
    split_pack(hv.x, hv.y, h0, l0);
    split_pack(hv.z, hv.w, h1, l1);
    reinterpret_cast<uint2*>(g_h_hi)[i4] = make_uint2(h0, h1);
    reinterpret_cast<uint2*>(g_h_lo)[i4] = make_uint2(l0, l1);
}

// ---------------------------------------------------------------------------
// QE-skew on tensor cores. Inputs pre-split bf16 (qhi/qlo, ehi/elo).
// smem: Q hi/lo (64x144B each) + E hi/lo = 36864 B
// ---------------------------------------------------------------------------
#define TILE_B 9216      // 64 rows * 144 B
#define QE2_SMEM (4*TILE_B)

__global__ void __launch_bounds__(128) qe_skew2_kernel(
    const __nv_bfloat16* __restrict__ qhi, const __nv_bfloat16* __restrict__ qlo,
    const __nv_bfloat16* __restrict__ ehi, const __nv_bfloat16* __restrict__ elo,
    float* __restrict__ SK)
{
    extern __shared__ char smembuf[];
    const uint32_t sb = smem_u32(smembuf);

    const int bh = blockIdx.y;
    const int b  = bh >> 3;
    const int h  = bh & 7;
    const int i0 = blockIdx.x * 64;
    const int tid  = threadIdx.x;      // 128
    const int wid  = tid >> 5;
    const int lane = tid & 31;
    const int tok0 = b * SEQ;
    const int hoff = h * DHEAD;
    const int wq = wid * 16;
    const int koff16 = (lane >> 4) * 16;

    // load Q hi/lo tiles
    #pragma unroll
    for (int t = 0; t < 8; t++) {
        int idx = tid + t*128;                 // [0,1024)
        int op = idx >> 9, rem = idx & 511;
        int r = rem >> 3, g = rem & 7;
        const __nv_bfloat16* src = (op ? qlo : qhi) + (size_t)(tok0 + i0 + r)*DMODEL + hoff + g*8;
        cp_async16(sb + op*TILE_B + r*144 + g*16, src);
    }
    CP_COMMIT(); CP_WAIT(0);
    __syncthreads();

    // hoist Q fragments
    uint32_t ahq[4][4], alq[4][4];
    #pragma unroll
    for (int kt = 0; kt < 4; kt++) {
        uint32_t qa = sb + (wq + (lane & 15))*144 + kt*32 + koff16;
        ldm_x4(ahq[kt][0], ahq[kt][1], ahq[kt][2], ahq[kt][3], qa);
        ldm_x4(alq[kt][0], alq[kt][1], alq[kt][2], alq[kt][3], qa + TILE_B);
    }

    float* skb = SK + ((size_t)bh << 20);
    const int row0 = i0 + wq + (lane >> 2);
    const int qc = (lane & 3) * 2;
    const int mt_lo = ((960 - i0) >> 6) << 6;
    const uint32_t eb = sb + 2*TILE_B;

    for (int mt = mt_lo; mt < 1024; mt += 64) {
        __syncthreads();
        #pragma unroll
        for (int t = 0; t < 8; t++) {
            int idx = tid + t*128;
            int op = idx >> 9, rem = idx & 511;
            int r = rem >> 3, g = rem & 7;
            const __nv_bfloat16* src = (op ? elo : ehi) + (size_t)(mt + r)*DHEAD + g*8;
            cp_async16(eb + op*TILE_B + r*144 + g*16, src);
        }
        CP_COMMIT(); CP_WAIT(0);
        __syncthreads();

        float s[8][4];
        #pragma unroll
        for (int n = 0; n < 8; n++)
            #pragma unroll
            for (int e = 0; e < 4; e++) s[n][e] = 0.f;

        #pragma unroll
        for (int kt = 0; kt < 4; kt++) {
            uint32_t bh2[8][2], bl2[8][2];
            #pragma unroll
            for (int p = 0; p < 4; p++) {
                uint32_t r0, r1, r2, r3;
                uint32_t ba = eb + (p*16 + (lane & 15))*144 + kt*32 + koff16;
                ldm_x4(r0, r1, r2, r3, ba);
                bh2[2*p][0] = r0; bh2[2*p][1] = r2; bh2[2*p+1][0] = r1; bh2[2*p+1][1] = r3;
                ldm_x4(r0, r1, r2, r3, ba + TILE_B);
                bl2[2*p][0] = r0; bl2[2*p][1] = r2; bl2[2*p+1][0] = r1; bl2[2*p+1][1] = r3;
            }
            #pragma unroll
            for (int n = 0; n < 8; n++) {
                mma_bf16(s[n][0], s[n][1], s[n][2], s[n][3],
                         ahq[kt][0], ahq[kt][1], ahq[kt][2], ahq[kt][3], bh2[n][0], bh2[n][1]);
                mma_bf16(s[n][0], s[n][1], s[n][2], s[n][3],
                         alq[kt][0], alq[kt][1], alq[kt][2], alq[kt][3], bh2[n][0], bh2[n][1]);
                mma_bf16(s[n][0], s[n][1], s[n][2], s[n][3],
                         ahq[kt][0], ahq[kt][1], ahq[kt][2], ahq[kt][3], bl2[n][0], bl2[n][1]);
            }
        }

        // skewed scatter: QE[i][m] -> SK[i][j = m-1023+i]
        #pragma unroll
        for (int n = 0; n < 8; n++) {
            int m = mt + 8*n + qc;
            int j0 = m - 1023 + row0;
            if (j0 >= 0)       { skb[((size_t)row0 << 10) + j0] = s[n][0];
                                 skb[((size_t)row0 << 10) + j0 + 1] = s[n][1]; }
            else if (j0 == -1)   skb[((size_t)row0 << 10)] = s[n][1];
            int j1 = j0 + 8;
            int r1 = row0 + 8;
            if (j1 >= 0)       { skb[((size_t)r1 << 10) + j1] = s[n][2];
                                 skb[((size_t)r1 << 10) + j1 + 1] = s[n][3]; }
            else if (j1 == -1)   skb[((size_t)r1 << 10)] = s[n][3];
        }
    }
}

// ---------------------------------------------------------------------------
// Flash attention on tensor cores, pre-split bf16 inputs, SINGLE-buffered K/V
// (55296 B smem) + __launch_bounds__(128,3) -> 3 CTAs/SM for cross-CTA overlap.
// ldmatrix.trans for V. Writes bf16 hi/lo split output.
// ---------------------------------------------------------------------------
#define AT2_SMEM (2*TILE_B + 4*TILE_B)   // Q hi/lo + one K/V stage = 55296 B

__global__ void __launch_bounds__(128, 3) attention2_kernel(
    const __nv_bfloat16* __restrict__ qhi, const __nv_bfloat16* __restrict__ qlo,
    const __nv_bfloat16* __restrict__ khi, const __nv_bfloat16* __restrict__ klo,
    const __nv_bfloat16* __restrict__ vhi, const __nv_bfloat16* __restrict__ vlo,
    const float* __restrict__ SK,
    __nv_bfloat16* __restrict__ Ohi, __nv_bfloat16* __restrict__ Olo)
{
    extern __shared__ char smembuf[];
    const uint32_t sb = smem_u32(smembuf);

    const int bh = blockIdx.y;
    const int b  = bh >> 3;
    const int h  = bh & 7;
    const int i0 = blockIdx.x * 64;
    const int tid  = threadIdx.x;      // 128
    const int wid  = tid >> 5;
    const int lane = tid & 31;
    const int tok0 = b * SEQ;
    const int hoff = h * DHEAD;
    const int wq = wid * 16;
    const int koff16 = (lane >> 4) * 16;

    const uint32_t kvb = sb + 2*TILE_B;    // single K/V buffer

    auto load_kv = [&](int jt) {
        const int j0 = jt * 64;
        #pragma unroll
        for (int t = 0; t < 16; t++) {
            int idx = tid + t*128;                 // [0,2048)
            int op = idx >> 9, rem = idx & 511;
            int r = rem >> 3, g = rem & 7;
            const __nv_bfloat16* src =
                (op == 0 ? khi : op == 1 ? klo : op == 2 ? vhi : vlo)
                + (size_t)(tok0 + j0 + r)*DMODEL + hoff + g*8;
            cp_async16(kvb + op*TILE_B + r*144 + g*16, src);
        }
        CP_COMMIT();
    };

    // Q tiles + first K/V
    #pragma unroll
    for (int t = 0; t < 8; t++) {
        int idx = tid + t*128;
        int op = idx >> 9, rem = idx & 511;
        int r = rem >> 3, g = rem & 7;
        const __nv_bfloat16* src = (op ? qlo : qhi) + (size_t)(tok0 + i0 + r)*DMODEL + hoff + g*8;
        cp_async16(sb + op*TILE_B + r*144 + g*16, src);
    }
    CP_COMMIT();
    load_kv(0);
    CP_WAIT(0);
    __syncthreads();

    // hoist Q fragments
    uint32_t ahq[4][4], alq[4][4];
    #pragma unroll
    for (int kt = 0; kt < 4; kt++) {
        uint32_t qa = sb + (wq + (lane & 15))*144 + kt*32 + koff16;
        ldm_x4(ahq[kt][0], ahq[kt][1], ahq[kt][2], ahq[kt][3], qa);
        ldm_x4(alq[kt][0], alq[kt][1], alq[kt][2], alq[kt][3], qa + TILE_B);
    }

    float m_i[2] = {-1e30f, -1e30f}, l_i[2] = {0.f, 0.f};
    float acc[8][4];
    #pragma unroll
    for (int n = 0; n < 8; n++)
        #pragma unroll
        for (int e = 0; e < 4; e++) acc[n][e] = 0.f;

    const float* skb = SK + ((size_t)bh << 20);
    const int row0 = i0 + wq + (lane >> 2);
    const int qc = (lane & 3) * 2;

    for (int jt = 0; jt < 16; jt++) {
        const int j0 = jt * 64;

        // ---- S = Q K^T (bf16x3) ----
        float s[8][4];
        #pragma unroll
        for (int n = 0; n < 8; n++)
            #pragma unroll
            for (int e = 0; e < 4; e++) s[n][e] = 0.f;

        #pragma unroll
        for (int kt = 0; kt < 4; kt++) {
            uint32_t bh2[8][2], bl2[8][2];
            #pragma unroll
            for (int p = 0; p < 4; p++) {
                uint32_t r0, r1, r2, r3;
                uint32_t ba = kvb + (p*16 + (lane & 15))*144 + kt*32 + koff16;
                ldm_x4(r0, r1, r2, r3, ba);
                bh2[2*p][0] = r0; bh2[2*p][1] = r2; bh2[2*p+1][0] = r1; bh2[2*p+1][1] = r3;
                ldm_x4(r0, r1, r2, r3, ba + TILE_B);
                bl2[2*p][0] = r0; bl2[2*p][1] = r2; bl2[2*p+1][0] = r1; bl2[2*p+1][1] = r3;
            }
            #pragma unroll
            for (int n = 0; n < 8; n++) {
                mma_bf16(s[n][0], s[n][1], s[n][2], s[n][3],
                         ahq[kt][0], ahq[kt][1], ahq[kt][2], ahq[kt][3], bh2[n][0], bh2[n][1]);
                mma_bf16(s[n][0], s[n][1], s[n][2], s[n][3],
                         alq[kt][0], alq[kt][1], alq[kt][2], alq[kt][3], bh2[n][0], bh2[n][1]);
                mma_bf16(s[n][0], s[n][1], s[n][2], s[n][3],
                         ahq[kt][0], ahq[kt][1], ahq[kt][2], ahq[kt][3], bl2[n][0], bl2[n][1]);
            }
        }

        // ---- rel term + scale ----
        #pragma unroll
        for (int n = 0; n < 8; n++) {
            int jc = j0 + 8*n + qc;
            const float* p0 = skb + ((size_t)row0 << 10) + jc;
            const float* p1 = p0 + (8 << 10);
            if (jc     <= row0)     s[n][0] += p0[0];
            if (jc + 1 <= row0)     s[n][1] += p0[1];
            if (jc     <= row0 + 8) s[n][2] += p1[0];
            if (jc + 1 <= row0 + 8) s[n][3] += p1[1];
            #pragma unroll
            for (int e = 0; e < 4; e++) s[n][e] *= INV_SQRT_DH;
        }

        // ---- online softmax ----
        #pragma unroll
        for (int rr = 0; rr < 2; rr++) {
            float mx = -1e30f;
            #pragma unroll
            for (int n = 0; n < 8; n++) {
                mx = fmaxf(mx, s[n][2*rr]);
                mx = fmaxf(mx, s[n][2*rr + 1]);
            }
            mx = fmaxf(mx, __shfl_xor_sync(0xffffffffu, mx, 1));
            mx = fmaxf(mx, __shfl_xor_sync(0xffffffffu, mx, 2));
            float mn = fmaxf(m_i[rr], mx);
            float alpha = __expf(m_i[rr] - mn);
            float ps = 0.f;
            #pragma unroll
            for (int n = 0; n < 8; n++) {
                float p0 = __expf(s[n][2*rr]     - mn);
                float p1 = __expf(s[n][2*rr + 1] - mn);
                s[n][2*rr] = p0; s[n][2*rr + 1] = p1;
                ps += p0 + p1;
            }
            ps += __shfl_xor_sync(0xffffffffu, ps, 1);
            ps += __shfl_xor_sync(0xffffffffu, ps, 2);
            l_i[rr] = l_i[rr] * alpha + ps;
            m_i[rr] = mn;
            #pragma unroll
            for (int dn = 0; dn < 8; dn++) {
                acc[dn][2*rr]     *= alpha;
                acc[dn][2*rr + 1] *= alpha;
            }
        }

        // ---- pack P ----
        uint32_t ph[8][2], pl[8][2];
        #pragma unroll
        for (int n = 0; n < 8; n++) {
            split_pack(s[n][0], s[n][1], ph[n][0], pl[n][0]);
            split_pack(s[n][2], s[n][3], ph[n][1], pl[n][1]);
        }

        // ---- O += P V (V via ldmatrix.trans) ----
        const uint32_t vb = kvb + 2*TILE_B;
        #pragma unroll
        for (int kt = 0; kt < 4; kt++) {
            uint32_t ah0 = ph[2*kt][0], ah1 = ph[2*kt][1], ah2 = ph[2*kt+1][0], ah3 = ph[2*kt+1][1];
            uint32_t al0 = pl[2*kt][0], al1 = pl[2*kt][1], al2 = pl[2*kt+1][0], al3 = pl[2*kt+1][1];
            uint32_t vh2[8][2], vl2[8][2];
            #pragma unroll
            for (int p = 0; p < 4; p++) {
                uint32_t r0, r1, r2, r3;
                uint32_t va = vb + (kt*16 + (lane & 15))*144 + p*32 + koff16;
                ldm_x4t(r0, r1, r2, r3, va);
                vh2[2*p][0] = r0; vh2[2*p][1] = r1; vh2[2*p+1][0] = r2; vh2[2*p+1][1] = r3;
                ldm_x4t(r0, r1, r2, r3, va + TILE_B);
                vl2[2*p][0] = r0; vl2[2*p][1] = r1; vl2[2*p+1][0] = r2; vl2[2*p+1][1] = r3;
            }
            #pragma unroll
            for (int dn = 0; dn < 8; dn++) {
                mma_bf16(acc[dn][0], acc[dn][1], acc[dn][2], acc[dn][3],
                         ah0, ah1, ah2, ah3, vh2[dn][0], vh2[dn][1]);
                mma_bf16(acc[dn][0], acc[dn][1], acc[dn][2], acc[dn][3],
                         al0, al1, al2, al3, vh2[dn][0], vh2[dn][1]);
                mma_bf16(acc[dn][0], acc[dn][1], acc[dn][2], acc[dn][3],
                         ah0, ah1, ah2, ah3, vl2[dn][0], vl2[dn][1]);
            }
        }

        // refill the single K/V buffer for jt+1
        if (jt + 1 < 16) {
            __syncthreads();
            load_kv(jt + 1);
            CP_WAIT(0);
            __syncthreads();
        }
    }

    // normalize + split-store
    #pragma unroll
    for (int rr = 0; rr < 2; rr++) {
        float inv = 1.f / l_i[rr];
        int row = row0 + rr*8;
        #pragma unroll
        for (int dn = 0; dn < 8; dn++) {
            float o0 = acc[dn][2*rr] * inv, o1 = acc[dn][2*rr + 1] * inv;
            uint32_t hi, lo;
            split_pack(o0, o1, hi, lo);
            size_t oaddr = (size_t)(tok0 + row)*DMODEL + hoff + 8*dn + qc;
            *reinterpret_cast<uint32_t*>(Ohi + oaddr) = hi;
            *reinterpret_cast<uint32_t*>(Olo + oaddr) = lo;
        }
    }
}

// ---------------------------------------------------------------------------
// y = LayerNorm(a + b) * scale + bias; emits fp32 y and bf16 hi/lo split.
// ---------------------------------------------------------------------------
__global__ void add_ln_kernel(const float* __restrict__ a, const float* __restrict__ b,
                              const float* __restrict__ scale, const float* __restrict__ bias,
                              float* __restrict__ y,
                              __nv_bfloat16* __restrict__ yhi, __nv_bfloat16* __restrict__ ylo) {
    const int t = blockIdx.x;
    const int tid = threadIdx.x;       // 128
    const int d4 = tid * 4;
    const size_t base = (size_t)t*DMODEL + d4;
    float4 av = *reinterpret_cast<const float4*>(a + base);
    float4 bv = *reinterpret_cast<const float4*>(b + base);
    float x[4] = {av.x + bv.x, av.y + bv.y, av.z + bv.z, av.w + bv.w};
    float sum = x[0] + x[1] + x[2] + x[3];
    __shared__ float red[4];
    #pragma unroll
    for (int o = 16; o > 0; o >>= 1) sum += __shfl_xor_sync(0xffffffffu, sum, o);
    if ((tid & 31) == 0) red[tid >> 5] = sum;
    __syncthreads();
    sum = red[0] + red[1] + red[2] + red[3];
    const float mu = sum * (1.f/512.f);
    float vs = 0.f;
    #pragma unroll
    for (int i = 0; i < 4; i++) { float dd = x[i] - mu; vs = fmaf(dd, dd, vs); }
    #pragma unroll
    for (int o = 16; o > 0; o >>= 1) vs += __shfl_xor_sync(0xffffffffu, vs, o);
    __shared__ float red2[4];
    if ((tid & 31) == 0) red2[tid >> 5] = vs;
    __syncthreads();
    vs = red2[0] + red2[1] + red2[2] + red2[3];
    const float rstd = rsqrtf(vs * (1.f/512.f) + 1e-6f);
    float o[4];
    #pragma unroll
    for (int i = 0; i < 4; i++)
        o[i] = (x[i] - mu) * rstd * scale[d4 + i] + bias[d4 + i];
    *reinterpret_cast<float4*>(y + base) = make_float4(o[0], o[1], o[2], o[3]);
    uint32_t h0, l0, h1, l1;
    split_pack(o[0], o[1], h0, l0);
    split_pack(o[2], o[3], h1, l1);
    *reinterpret_cast<uint2*>(yhi + base) = make_uint2(h0, h1);
    *reinterpret_cast<uint2*>(ylo + base) = make_uint2(l0, l1);
}

// ---------------------------------------------------------------------------
// out[b,o] = tanh(h[b,0,:] . Wf[:,o] + bf[o])
// ---------------------------------------------------------------------------
__global__ void head_kernel(const float* __restrict__ Wf, const float* __restrict__ bf,
                            float* __restrict__ out) {
    const int w = threadIdx.x >> 5;
    const int lane = threadIdx.x & 31;
    const int b = w >> 1, o = w & 1;
    const float* hr = g_h + (size_t)b*SEQ*DMODEL;
    float sum = 0.f;
    #pragma unroll
    for (int d = lane; d < DMODEL; d += 32)
        sum = fmaf(hr[d], Wf[d*2 + o], sum);
    #pragma unroll
    for (int off = 16; off > 0; off >>= 1) sum += __shfl_xor_sync(0xffffffffu, sum, off);
    if (lane == 0) out[b*2 + o] = tanhf(sum + bf[o]);
}

// ---------------------------------------------------------------------------
// Launch
// ---------------------------------------------------------------------------
extern "C" void kernel_launch(void* const* d_in, const int* in_sizes, int n_in,
                              void* d_out, int out_size) {
    const int*   x    = (const int*)  d_in[0];
    const float* emb  = (const float*)d_in[1];
    const float* pos  = (const float*)d_in[2];
    const float* Wq   = (const float*)d_in[3];
    const float* bq   = (const float*)d_in[4];
    const float* Wk   = (const float*)d_in[5];
    const float* bk   = (const float*)d_in[6];
    const float* Wv   = (const float*)d_in[7];
    const float* bv   = (const float*)d_in[8];
    const float* Wo   = (const float*)d_in[9];
    const float* bo   = (const float*)d_in[10];
    const float* E    = (const float*)d_in[11];
    const float* W1   = (const float*)d_in[12];
    const float* b1   = (const float*)d_in[13];
    const float* W2   = (const float*)d_in[14];
    const float* b2   = (const float*)d_in[15];
    const float* ln1s = (const float*)d_in[16];
    const float* ln1b = (const float*)d_in[17];
    const float* ln2s = (const float*)d_in[18];
    const float* ln2b = (const float*)d_in[19];
    const float* Wf   = (const float*)d_in[20];
    const float* bf   = (const float*)d_in[21];
    float* out = (float*)d_out;

    float *h, *h1, *ffn, *sk;
    cudaGetSymbolAddress((void**)&h,   g_h);
    cudaGetSymbolAddress((void**)&h1,  g_h1);
    cudaGetSymbolAddress((void**)&ffn, g_ffn);
    cudaGetSymbolAddress((void**)&sk,  g_sk);

    __nv_bfloat16 *hhi, *hlo, *qh, *ql, *kh, *kl, *vh, *vl;
    __nv_bfloat16 *athi, *atlo, *h1hi, *h1lo, *mdhi, *mdlo, *ehi, *elo;
    __nv_bfloat16 *w4h, *w4l, *w1h, *w1l, *w2h, *w2l;
    cudaGetSymbolAddress((void**)&hhi,  g_h_hi);
    cudaGetSymbolAddress((void**)&hlo,  g_h_lo);
    cudaGetSymbolAddress((void**)&qh,   g_q_hi);
    cudaGetSymbolAddress((void**)&ql,   g_q_lo);
    cudaGetSymbolAddress((void**)&kh,   g_k_hi);
    cudaGetSymbolAddress((void**)&kl,   g_k_lo);
    cudaGetSymbolAddress((void**)&vh,   g_v_hi);
    cudaGetSymbolAddress((void**)&vl,   g_v_lo);
    cudaGetSymbolAddress((void**)&athi, g_attn_hi);
    cudaGetSymbolAddress((void**)&atlo, g_attn_lo);
    cudaGetSymbolAddress((void**)&h1hi, g_h1_hi);
    cudaGetSymbolAddress((void**)&h1lo, g_h1_lo);
    cudaGetSymbolAddress((void**)&mdhi, g_mid_hi);
    cudaGetSymbolAddress((void**)&mdlo, g_mid_lo);
    cudaGetSymbolAddress((void**)&ehi,  g_e_hi);
    cudaGetSymbolAddress((void**)&elo,  g_e_lo);
    cudaGetSymbolAddress((void**)&w4h, g_w4_hi);
    cudaGetSymbolAddress((void**)&w4l, g_w4_lo);
    cudaGetSymbolAddress((void**)&w1h, g_w1_hi);
    cudaGetSymbolAddress((void**)&w1l, g_w1_lo);
    cudaGetSymbolAddress((void**)&w2h, g_w2_hi);
    cudaGetSymbolAddress((void**)&w2l, g_w2_lo);

    cudaFuncSetAttribute(attention2_kernel, cudaFuncAttributeMaxDynamicSharedMemorySize, AT2_SMEM);
    cudaFuncSetAttribute(qe_skew2_kernel,   cudaFuncAttributeMaxDynamicSharedMemorySize, QE2_SMEM);
    cudaFuncSetAttribute((const void*)mma_gemm_kernel<0,false>, cudaFuncAttributeMaxDynamicSharedMemorySize, MMA_SMEM);
    cudaFuncSetAttribute((const void*)mma_gemm_kernel<1,true>,  cudaFuncAttributeMaxDynamicSharedMemorySize, MMA_SMEM);
    cudaFuncSetAttribute((const void*)mma_gemm_qkv_kernel,      cudaFuncAttributeMaxDynamicSharedMemorySize, MMA_SMEM);

    const size_t SZ = (size_t)DMODEL * DMODEL;      // 262144

    wconv_t_kernel<<<dim3(16,16,NLAYER), 256>>>(Wq, w4h + 0*SZ, w4l + 0*SZ, DMODEL, DMODEL, SZ, 4*SZ);
    wconv_t_kernel<<<dim3(16,16,NLAYER), 256>>>(Wk, w4h + 1*SZ, w4l + 1*SZ, DMODEL, DMODEL, SZ, 4*SZ);
    wconv_t_kernel<<<dim3(16,16,NLAYER), 256>>>(Wv, w4h + 2*SZ, w4l + 2*SZ, DMODEL, DMODEL, SZ, 4*SZ);
    wconv_t_kernel<<<dim3(16,16,NLAYER), 256>>>(Wo, w4h + 3*SZ, w4l + 3*SZ, DMODEL, DMODEL, SZ, 4*SZ);
    wconv_t_kernel<<<dim3(64,16,NLAYER), 256>>>(W1, w1h, w1l, DMODEL, DINNER,
                                                (size_t)DMODEL*DINNER, (size_t)DINNER*DMODEL);
    wconv_t_kernel<<<dim3(16,64,NLAYER), 256>>>(W2, w2h, w2l, DINNER, DMODEL,
                                                (size_t)DINNER*DMODEL, (size_t)DMODEL*DINNER);
    econv_kernel<<<NLAYER*SEQ*DHEAD/4/256, 256>>>(E);

    embed_kernel<<<NTOK*DMODEL/4/256, 256>>>(x, emb, pos);

    for (int l = 0; l < NLAYER; l++) {
        const __nv_bfloat16* l4h = w4h + (size_t)l*4*SZ;
        const __nv_bfloat16* l4l = w4l + (size_t)l*4*SZ;

        mma_gemm_qkv_kernel<<<dim3(4,32,3), 256, MMA_SMEM>>>(hhi, hlo, l4h, l4l,
            bq + l*DMODEL, bk + l*DMODEL, bv + l*DMODEL, qh, ql, kh, kl, vh, vl);

        qe_skew2_kernel<<<dim3(16,32), 128, QE2_SMEM>>>(qh, ql,
            ehi + (size_t)l*SEQ*DHEAD, elo + (size_t)l*SEQ*DHEAD, sk);
        attention2_kernel<<<dim3(16,32), 128, AT2_SMEM>>>(qh, ql, kh, kl, vh, vl, sk, athi, atlo);

        mma_gemm_kernel<0,false><<<dim3(4,32), 256, MMA_SMEM>>>(athi, atlo, l4h + 3*SZ, l4l + 3*SZ,
            bo + l*DMODEL, ffn, nullptr, nullptr, NTOK, DMODEL, DMODEL);
        add_ln_kernel<<<NTOK, 128>>>(ffn, h, ln1s + l*DMODEL, ln1b + l*DMODEL, h1, h1hi, h1lo);

        mma_gemm_kernel<1,true><<<dim3(16,32), 256, MMA_SMEM>>>(h1hi, h1lo,
            w1h + (size_t)l*DINNER*DMODEL, w1l + (size_t)l*DINNER*DMODEL,
            b1 + l*DINNER, nullptr, mdhi, mdlo, NTOK, DINNER, DMODEL);

        mma_gemm_kernel<0,false><<<dim3(4,32), 256, MMA_SMEM>>>(mdhi, mdlo,
            w2h + (size_t)l*DMODEL*DINNER, w2l + (size_t)l*DMODEL*DINNER,
            b2 + l*DMODEL, ffn, nullptr, nullptr, NTOK, DMODEL, DINNER);
        add_ln_kernel<<<NTOK, 128>>>(h1, ffn, ln2s + l*DMODEL, ln2b + l*DMODEL, h, hhi, hlo);
    }

    head_kernel<<<1, 256>>>(Wf, bf, out);
}

// round 11
// speedup vs baseline: 1.0212x; 1.0212x over previous
#include <cuda_runtime.h>
#include <cuda_bf16.h>
#include <math.h>
#include <stdint.h>

// ---------------------------------------------------------------------------
// Problem constants
// ---------------------------------------------------------------------------
#define BATCH 4
#define SEQ   1024
#define DMODEL 512
#define DINNER 2048
#define NHEAD 8
#define DHEAD 64
#define NLAYER 6
#define NTOK (BATCH*SEQ)          // 4096
#define SQRT_D 22.627416997969522f
#define INV_SQRT_DH 0.125f

// ---------------------------------------------------------------------------
// Scratch (device globals: no allocations allowed)
// ---------------------------------------------------------------------------
__device__ float g_h   [NTOK*DMODEL];
__device__ float g_h1  [NTOK*DMODEL];
__device__ float g_ffn [NTOK*DMODEL];
__device__ float g_sk  [32u*1024u*1024u];   // SK[bh][i][j] = q_i . E[1023-i+j], j<=i

// bf16 split operand buffers
__device__ __nv_bfloat16 g_h_hi   [NTOK*DMODEL];
__device__ __nv_bfloat16 g_h_lo   [NTOK*DMODEL];
__device__ __nv_bfloat16 g_q_hi   [NTOK*DMODEL];
__device__ __nv_bfloat16 g_q_lo   [NTOK*DMODEL];
__device__ __nv_bfloat16 g_k_hi   [NTOK*DMODEL];
__device__ __nv_bfloat16 g_k_lo   [NTOK*DMODEL];
__device__ __nv_bfloat16 g_v_hi   [NTOK*DMODEL];
__device__ __nv_bfloat16 g_v_lo   [NTOK*DMODEL];
__device__ __nv_bfloat16 g_attn_hi[NTOK*DMODEL];
__device__ __nv_bfloat16 g_attn_lo[NTOK*DMODEL];
__device__ __nv_bfloat16 g_h1_hi  [NTOK*DMODEL];
__device__ __nv_bfloat16 g_h1_lo  [NTOK*DMODEL];
__device__ __nv_bfloat16 g_mid_hi [NTOK*DINNER];
__device__ __nv_bfloat16 g_mid_lo [NTOK*DINNER];
__device__ __nv_bfloat16 g_e_hi   [NLAYER*SEQ*DHEAD];
__device__ __nv_bfloat16 g_e_lo   [NLAYER*SEQ*DHEAD];

__device__ __nv_bfloat16 g_w4_hi[NLAYER*4*DMODEL*DMODEL];   // q,k,v,o transposed [N,K]
__device__ __nv_bfloat16 g_w4_lo[NLAYER*4*DMODEL*DMODEL];
__device__ __nv_bfloat16 g_w1_hi[NLAYER*DINNER*DMODEL];     // W1^T
__device__ __nv_bfloat16 g_w1_lo[NLAYER*DINNER*DMODEL];
__device__ __nv_bfloat16 g_w2_hi[NLAYER*DMODEL*DINNER];     // W2^T
__device__ __nv_bfloat16 g_w2_lo[NLAYER*DMODEL*DINNER];

// ---------------------------------------------------------------------------
// PTX helpers
// ---------------------------------------------------------------------------
__device__ __forceinline__ uint32_t smem_u32(const void* p) {
    uint32_t a;
    asm("{ .reg .u64 t; cvta.to.shared.u64 t, %1; cvt.u32.u64 %0, t; }" : "=r"(a) : "l"(p));
    return a;
}

__device__ __forceinline__ void cp_async16(uint32_t dst, const void* src) {
    asm volatile("cp.async.cg.shared.global [%0], [%1], 16;" :: "r"(dst), "l"(src));
}
#define CP_COMMIT() asm volatile("cp.async.commit_group;" ::: "memory")
#define CP_WAIT(N)  asm volatile("cp.async.wait_group %0;" :: "n"(N) : "memory")

__device__ __forceinline__ void ldm_x4(uint32_t& r0, uint32_t& r1, uint32_t& r2, uint32_t& r3,
                                       uint32_t addr) {
    asm volatile("ldmatrix.sync.aligned.m8n8.x4.shared.b16 {%0,%1,%2,%3}, [%4];"
                 : "=r"(r0), "=r"(r1), "=r"(r2), "=r"(r3) : "r"(addr));
}
__device__ __forceinline__ void ldm_x4t(uint32_t& r0, uint32_t& r1, uint32_t& r2, uint32_t& r3,
                                        uint32_t addr) {
    asm volatile("ldmatrix.sync.aligned.m8n8.x4.trans.shared.b16 {%0,%1,%2,%3}, [%4];"
                 : "=r"(r0), "=r"(r1), "=r"(r2), "=r"(r3) : "r"(addr));
}

__device__ __forceinline__ void mma_bf16(float& c0, float& c1, float& c2, float& c3,
                                         uint32_t a0, uint32_t a1, uint32_t a2, uint32_t a3,
                                         uint32_t b0, uint32_t b1) {
    asm volatile(
        "mma.sync.aligned.m16n8k16.row.col.f32.bf16.bf16.f32 "
        "{%0,%1,%2,%3}, {%4,%5,%6,%7}, {%8,%9}, {%0,%1,%2,%3};"
        : "+f"(c0), "+f"(c1), "+f"(c2), "+f"(c3)
        : "r"(a0), "r"(a1), "r"(a2), "r"(a3), "r"(b0), "r"(b1));
}

__device__ __forceinline__ void split_pack(float x, float y, uint32_t& hi, uint32_t& lo) {
    __nv_bfloat16 bx = __float2bfloat16(x), by = __float2bfloat16(y);
    hi = (uint32_t)__bfloat16_as_ushort(bx) | ((uint32_t)__bfloat16_as_ushort(by) << 16);
    __nv_bfloat16 rx = __float2bfloat16(x - __bfloat162float(bx));
    __nv_bfloat16 ry = __float2bfloat16(y - __bfloat162float(by));
    lo = (uint32_t)__bfloat16_as_ushort(rx) | ((uint32_t)__bfloat16_as_ushort(ry) << 16);
}

// ---------------------------------------------------------------------------
// Fused-split tensor-core GEMM: C = (Ahi+Alo)[M,K] @ (Bhi+Blo)^T[N,K] + bias
// CTA tile 128x64, 128 threads (4 warps of 64x32, 2x2 grid). BK=32, 2-stage.
// Stage: Ahi|Alo (128x80B) + Bhi|Blo (64x80B) = 30720 B; 2 stages = 61440 B.
// Small CTA => 2-3 CTAs/SM fit in BOTH regs and smem (no launch-bounds cap).
// OMODE: 0 = fp32 out, 1 = bf16 hi/lo split out.
// ---------------------------------------------------------------------------
#define OPB_A 10240             // A operand tile bytes (128 rows * 80 B)
#define OPB_B 5120              // B operand tile bytes (64 rows * 80 B)
#define STG_BYTES (2*OPB_A + 2*OPB_B)   // 30720
#define MMA_SMEM  (2*STG_BYTES)         // 61440

template<int OMODE, bool RELU>
__device__ __forceinline__ void mma_gemm_body(
    const __nv_bfloat16* __restrict__ Ahi, const __nv_bfloat16* __restrict__ Alo,
    const __nv_bfloat16* __restrict__ Bhi, const __nv_bfloat16* __restrict__ Blo,
    const float* __restrict__ bias, float* __restrict__ C,
    __nv_bfloat16* __restrict__ Chi, __nv_bfloat16* __restrict__ Clo,
    int M, int N, int K)
{
    extern __shared__ char smem[];
    const uint32_t sb = smem_u32(smem);
    const int tid  = threadIdx.x;         // 128
    const int wid  = tid >> 5;            // 0..3
    const int lane = tid & 31;
    const int wm   = (wid & 1) * 64;
    const int wn   = (wid >> 1) * 32;
    const int m0 = blockIdx.y * 128;
    const int n0 = blockIdx.x * 64;

    const int S = K >> 5;                 // BK=32 stages

    float acc[4][4][4];
    #pragma unroll
    for (int i = 0; i < 4; i++)
        #pragma unroll
        for (int j = 0; j < 4; j++)
            #pragma unroll
            for (int e = 0; e < 4; e++) acc[i][j][e] = 0.f;

    auto load_stage = [&](int st) {
        const int k0 = st << 5;
        const uint32_t base = sb + (st & 1) * STG_BYTES;
        #pragma unroll
        for (int i = 0; i < 12; i++) {
            int idx = tid + i*128;                 // [0,1536)
            if (idx < 1024) {                      // A hi/lo: 2 x 128 rows x 4 chunks
                int op = idx >> 9, rem = idx & 511;
                int r = rem >> 2, g = rem & 3;
                const __nv_bfloat16* src = (op ? Alo : Ahi) + (size_t)(m0 + r)*K + k0 + g*8;
                cp_async16(base + op*OPB_A + r*80 + g*16, src);
            } else {                               // B hi/lo: 2 x 64 rows x 4 chunks
                int j = idx - 1024;
                int op = j >> 8, rem = j & 255;
                int r = rem >> 2, g = rem & 3;
                const __nv_bfloat16* src = (op ? Blo : Bhi) + (size_t)(n0 + r)*K + k0 + g*8;
                cp_async16(base + 2*OPB_A + op*OPB_B + r*80 + g*16, src);
            }
        }
        CP_COMMIT();
    };

    load_stage(0);
    if (S > 1) load_stage(1);

    const int a_row = lane & 15;
    const int koff16 = (lane >> 4) * 16;

    for (int st = 0; st < S; ++st) {
        if (st + 1 < S) { CP_WAIT(1); }
        else            { CP_WAIT(0); }
        __syncthreads();

        const uint32_t base = sb + (st & 1) * STG_BYTES;

        #pragma unroll
        for (int ks = 0; ks < 2; ++ks) {
            uint32_t ah[4][4], al[4][4], bh[4][2], bl[4][2];
            #pragma unroll
            for (int mi = 0; mi < 4; ++mi) {
                uint32_t aa = base + (wm + mi*16 + a_row)*80 + ks*32 + koff16;
                ldm_x4(ah[mi][0], ah[mi][1], ah[mi][2], ah[mi][3], aa);
                ldm_x4(al[mi][0], al[mi][1], al[mi][2], al[mi][3], aa + OPB_A);
            }
            #pragma unroll
            for (int p = 0; p < 2; ++p) {
                uint32_t r0, r1, r2, r3;
                uint32_t ba = base + 2*OPB_A + (wn + p*16 + a_row)*80 + ks*32 + koff16;
                ldm_x4(r0, r1, r2, r3, ba);
                bh[2*p][0] = r0; bh[2*p][1] = r2; bh[2*p+1][0] = r1; bh[2*p+1][1] = r3;
                ldm_x4(r0, r1, r2, r3, ba + OPB_B);
                bl[2*p][0] = r0; bl[2*p][1] = r2; bl[2*p+1][0] = r1; bl[2*p+1][1] = r3;
            }
            #pragma unroll
            for (int mi = 0; mi < 4; ++mi)
                #pragma unroll
                for (int ni = 0; ni < 4; ++ni) {
                    mma_bf16(acc[mi][ni][0], acc[mi][ni][1], acc[mi][ni][2], acc[mi][ni][3],
                             ah[mi][0], ah[mi][1], ah[mi][2], ah[mi][3], bh[ni][0], bh[ni][1]);
                    mma_bf16(acc[mi][ni][0], acc[mi][ni][1], acc[mi][ni][2], acc[mi][ni][3],
                             al[mi][0], al[mi][1], al[mi][2], al[mi][3], bh[ni][0], bh[ni][1]);
                    mma_bf16(acc[mi][ni][0], acc[mi][ni][1], acc[mi][ni][2], acc[mi][ni][3],
                             ah[mi][0], ah[mi][1], ah[mi][2], ah[mi][3], bl[ni][0], bl[ni][1]);
                }
        }
        __syncthreads();
        if (st + 2 < S) load_stage(st + 2);
    }

    const int tg = lane >> 2;
    const int tc = (lane & 3) * 2;
    #pragma unroll
    for (int ni = 0; ni < 4; ++ni) {
        const int col = n0 + wn + ni*8 + tc;
        const float bz0 = bias[col], bz1 = bias[col + 1];
        #pragma unroll
        for (int mi = 0; mi < 4; ++mi) {
            const int row = m0 + wm + mi*16 + tg;
            float v0 = acc[mi][ni][0] + bz0, v1 = acc[mi][ni][1] + bz1;
            float v2 = acc[mi][ni][2] + bz0, v3 = acc[mi][ni][3] + bz1;
            if (RELU) {
                v0 = fmaxf(v0, 0.f); v1 = fmaxf(v1, 0.f);
                v2 = fmaxf(v2, 0.f); v3 = fmaxf(v3, 0.f);
            }
            if (OMODE == 0) {
                *reinterpret_cast<float2*>(C + (size_t)row*N + col) = make_float2(v0, v1);
                *reinterpret_cast<float2*>(C + (size_t)(row + 8)*N + col) = make_float2(v2, v3);
            } else {
                uint32_t h0, l0, h1, l1;
                split_pack(v0, v1, h0, l0);
                split_pack(v2, v3, h1, l1);
                *reinterpret_cast<uint32_t*>(Chi + (size_t)row*N + col) = h0;
                *reinterpret_cast<uint32_t*>(Clo + (size_t)row*N + col) = l0;
                *reinterpret_cast<uint32_t*>(Chi + (size_t)(row + 8)*N + col) = h1;
                *reinterpret_cast<uint32_t*>(Clo + (size_t)(row + 8)*N + col) = l1;
            }
        }
    }
}

template<int OMODE, bool RELU>
__global__ void __launch_bounds__(128) mma_gemm_kernel(
    const __nv_bfloat16* __restrict__ Ahi, const __nv_bfloat16* __restrict__ Alo,
    const __nv_bfloat16* __restrict__ Bhi, const __nv_bfloat16* __restrict__ Blo,
    const float* __restrict__ bias, float* __restrict__ C,
    __nv_bfloat16* __restrict__ Chi, __nv_bfloat16* __restrict__ Clo,
    int M, int N, int K)
{
    mma_gemm_body<OMODE, RELU>(Ahi, Alo, Bhi, Blo, bias, C, Chi, Clo, M, N, K);
}

// QKV fused: split bf16 outputs for q,k,v
__global__ void __launch_bounds__(128) mma_gemm_qkv_kernel(
    const __nv_bfloat16* __restrict__ Ahi, const __nv_bfloat16* __restrict__ Alo,
    const __nv_bfloat16* __restrict__ Whi, const __nv_bfloat16* __restrict__ Wlo,
    const float* __restrict__ bq, const float* __restrict__ bk, const float* __restrict__ bv,
    __nv_bfloat16* __restrict__ qh, __nv_bfloat16* __restrict__ ql,
    __nv_bfloat16* __restrict__ kh, __nv_bfloat16* __restrict__ kl,
    __nv_bfloat16* __restrict__ vh, __nv_bfloat16* __restrict__ vl)
{
    const int z = blockIdx.z;
    const size_t woff = (size_t)z * DMODEL * DMODEL;
    const float* bias = (z == 0) ? bq : (z == 1) ? bk : bv;
    __nv_bfloat16* Chi = (z == 0) ? qh : (z == 1) ? kh : vh;
    __nv_bfloat16* Clo = (z == 0) ? ql : (z == 1) ? kl : vl;
    mma_gemm_body<1, false>(Ahi, Alo, Whi + woff, Wlo + woff, bias, nullptr,
                            Chi, Clo, NTOK, DMODEL, DMODEL);
}

// ---------------------------------------------------------------------------
// Weight transpose + split: W[K,N] fp32 -> Whi/Wlo[N,K] bf16. z = layer.
// ---------------------------------------------------------------------------
__global__ void wconv_t_kernel(const float* __restrict__ W, __nv_bfloat16* __restrict__ Whi,
                               __nv_bfloat16* __restrict__ Wlo, int K, int N,
                               size_t strideW, size_t strideO) {
    __shared__ float t[32][33];
    const int l = blockIdx.z;
    W += (size_t)l * strideW; Whi += (size_t)l * strideO; Wlo += (size_t)l * strideO;
    const int tx = threadIdx.x & 31, ty = threadIdx.x >> 5;
    const int kb = blockIdx.y * 32, nb = blockIdx.x * 32;
    #pragma unroll
    for (int i = ty; i < 32; i += 8)
        t[i][tx] = W[(size_t)(kb + i)*N + nb + tx];
    __syncthreads();
    #pragma unroll
    for (int i = ty; i < 32; i += 8) {
        float x = t[tx][i];
        __nv_bfloat16 h = __float2bfloat16(x);
        __nv_bfloat16 lo = __float2bfloat16(x - __bfloat162float(h));
        size_t o = (size_t)(nb + i)*K + kb + tx;
        Whi[o] = h; Wlo[o] = lo;
    }
}

// E split (all layers): fp32 -> hi/lo bf16
__global__ void econv_kernel(const float* __restrict__ E) {
    int i4 = blockIdx.x * blockDim.x + threadIdx.x;   // [0, L*SEQ*DHEAD/4)
    float4 x = reinterpret_cast<const float4*>(E)[i4];
    uint32_t h0, l0, h1, l1;
    split_pack(x.x, x.y, h0, l0);
    split_pack(x.z, x.w, h1, l1);
    reinterpret_cast<uint2*>(g_e_hi)[i4] = make_uint2(h0, h1);
    reinterpret_cast<uint2*>(g_e_lo)[i4] = make_uint2(l0, l1);
}

// ---------------------------------------------------------------------------
// Embedding: h = emb[x]*sqrt(D) + pos; also emit bf16 hi/lo split.
// ---------------------------------------------------------------------------
__global__ void embed_kernel(const int* __restrict__ x, const float* __restrict__ emb,
                             const float* __restrict__ pos) {
    int i4 = blockIdx.x * blockDim.x + threadIdx.x;
    int idx = i4 * 4;
    int t = idx >> 9;
    int d = idx & 511;
    int s = t & (SEQ-1);
    int tok = x[t];
    float4 e = *reinterpret_cast<const float4*>(&emb[(size_t)tok*DMODEL + d]);
    float4 p = *reinterpret_cast<const float4*>(&pos[(size_t)s*DMODEL + d]);
    float4 hv = make_float4(e.x*SQRT_D + p.x, e.y*SQRT_D + p.y,
                            e.z*SQRT_D + p.z, e.w*SQRT_D + p.w);
    *reinterpret_cast<float4*>(&g_h[idx]) = hv;
    uint32_t h0, l0, h1, l1;
    split_pack(hv.x, hv.y, h0, l0);
    split_pack(hv.z, hv.w, h1, l1);
    reinterpret_cast<uint2*>(g_h_hi)[i4] = make_uint2(h0, h1);
    reinterpret_cast<uint2*>(g_h_lo)[i4] = make_uint2(l0, l1);
}

// ---------------------------------------------------------------------------
// QE-skew on tensor cores. Inputs pre-split bf16 (qhi/qlo, ehi/elo).
// smem: Q hi/lo (64x144B each) + E hi/lo = 36864 B
// ---------------------------------------------------------------------------
#define TILE_B 9216      // 64 rows * 144 B
#define QE2_SMEM (4*TILE_B)

__global__ void __launch_bounds__(128) qe_skew2_kernel(
    const __nv_bfloat16* __restrict__ qhi, const __nv_bfloat16* __restrict__ qlo,
    const __nv_bfloat16* __restrict__ ehi, const __nv_bfloat16* __restrict__ elo,
    float* __restrict__ SK)
{
    extern __shared__ char smembuf[];
    const uint32_t sb = smem_u32(smembuf);

    const int bh = blockIdx.y;
    const int b  = bh >> 3;
    const int h  = bh & 7;
    const int i0 = blockIdx.x * 64;
    const int tid  = threadIdx.x;      // 128
    const int wid  = tid >> 5;
    const int lane = tid & 31;
    const int tok0 = b * SEQ;
    const int hoff = h * DHEAD;
    const int wq = wid * 16;
    const int koff16 = (lane >> 4) * 16;

    // load Q hi/lo tiles
    #pragma unroll
    for (int t = 0; t < 8; t++) {
        int idx = tid + t*128;                 // [0,1024)
        int op = idx >> 9, rem = idx & 511;
        int r = rem >> 3, g = rem & 7;
        const __nv_bfloat16* src = (op ? qlo : qhi) + (size_t)(tok0 + i0 + r)*DMODEL + hoff + g*8;
        cp_async16(sb + op*TILE_B + r*144 + g*16, src);
    }
    CP_COMMIT(); CP_WAIT(0);
    __syncthreads();

    // hoist Q fragments
    uint32_t ahq[4][4], alq[4][4];
    #pragma unroll
    for (int kt = 0; kt < 4; kt++) {
        uint32_t qa = sb + (wq + (lane & 15))*144 + kt*32 + koff16;
        ldm_x4(ahq[kt][0], ahq[kt][1], ahq[kt][2], ahq[kt][3], qa);
        ldm_x4(alq[kt][0], alq[kt][1], alq[kt][2], alq[kt][3], qa + TILE_B);
    }

    float* skb = SK + ((size_t)bh << 20);
    const int row0 = i0 + wq + (lane >> 2);
    const int qc = (lane & 3) * 2;
    const int mt_lo = ((960 - i0) >> 6) << 6;
    const uint32_t eb = sb + 2*TILE_B;

    for (int mt = mt_lo; mt < 1024; mt += 64) {
        __syncthreads();
        #pragma unroll
        for (int t = 0; t < 8; t++) {
            int idx = tid + t*128;
            int op = idx >> 9, rem = idx & 511;
            int r = rem >> 3, g = rem & 7;
            const __nv_bfloat16* src = (op ? elo : ehi) + (size_t)(mt + r)*DHEAD + g*8;
            cp_async16(eb + op*TILE_B + r*144 + g*16, src);
        }
        CP_COMMIT(); CP_WAIT(0);
        __syncthreads();

        float s[8][4];
        #pragma unroll
        for (int n = 0; n < 8; n++)
            #pragma unroll
            for (int e = 0; e < 4; e++) s[n][e] = 0.f;

        #pragma unroll
        for (int kt = 0; kt < 4; kt++) {
            uint32_t bh2[8][2], bl2[8][2];
            #pragma unroll
            for (int p = 0; p < 4; p++) {
                uint32_t r0, r1, r2, r3;
                uint32_t ba = eb + (p*16 + (lane & 15))*144 + kt*32 + koff16;
                ldm_x4(r0, r1, r2, r3, ba);
                bh2[2*p][0] = r0; bh2[2*p][1] = r2; bh2[2*p+1][0] = r1; bh2[2*p+1][1] = r3;
                ldm_x4(r0, r1, r2, r3, ba + TILE_B);
                bl2[2*p][0] = r0; bl2[2*p][1] = r2; bl2[2*p+1][0] = r1; bl2[2*p+1][1] = r3;
            }
            #pragma unroll
            for (int n = 0; n < 8; n++) {
                mma_bf16(s[n][0], s[n][1], s[n][2], s[n][3],
                         ahq[kt][0], ahq[kt][1], ahq[kt][2], ahq[kt][3], bh2[n][0], bh2[n][1]);
                mma_bf16(s[n][0], s[n][1], s[n][2], s[n][3],
                         alq[kt][0], alq[kt][1], alq[kt][2], alq[kt][3], bh2[n][0], bh2[n][1]);
                mma_bf16(s[n][0], s[n][1], s[n][2], s[n][3],
                         ahq[kt][0], ahq[kt][1], ahq[kt][2], ahq[kt][3], bl2[n][0], bl2[n][1]);
            }
        }

        // skewed scatter: QE[i][m] -> SK[i][j = m-1023+i]
        #pragma unroll
        for (int n = 0; n < 8; n++) {
            int m = mt + 8*n + qc;
            int j0 = m - 1023 + row0;
            if (j0 >= 0)       { skb[((size_t)row0 << 10) + j0] = s[n][0];
                                 skb[((size_t)row0 << 10) + j0 + 1] = s[n][1]; }
            else if (j0 == -1)   skb[((size_t)row0 << 10)] = s[n][1];
            int j1 = j0 + 8;
            int r1 = row0 + 8;
            if (j1 >= 0)       { skb[((size_t)r1 << 10) + j1] = s[n][2];
                                 skb[((size_t)r1 << 10) + j1 + 1] = s[n][3]; }
            else if (j1 == -1)   skb[((size_t)r1 << 10)] = s[n][3];
        }
    }
}

// ---------------------------------------------------------------------------
// Flash attention on tensor cores, pre-split bf16 inputs, double-buffered K/V,
// ldmatrix.trans for V. Writes bf16 hi/lo split output.
// smem: Q hi/lo + 2 stages x (Khi,Klo,Vhi,Vlo) = 2*9216 + 2*4*9216 = 92160 B
// ---------------------------------------------------------------------------
#define AT2_SMEM (2*TILE_B + 2*4*TILE_B)

__global__ void __launch_bounds__(128) attention2_kernel(
    const __nv_bfloat16* __restrict__ qhi, const __nv_bfloat16* __restrict__ qlo,
    const __nv_bfloat16* __restrict__ khi, const __nv_bfloat16* __restrict__ klo,
    const __nv_bfloat16* __restrict__ vhi, const __nv_bfloat16* __restrict__ vlo,
    const float* __restrict__ SK,
    __nv_bfloat16* __restrict__ Ohi, __nv_bfloat16* __restrict__ Olo)
{
    extern __shared__ char smembuf[];
    const uint32_t sb = smem_u32(smembuf);

    const int bh = blockIdx.y;
    const int b  = bh >> 3;
    const int h  = bh & 7;
    const int i0 = blockIdx.x * 64;
    const int tid  = threadIdx.x;      // 128
    const int wid  = tid >> 5;
    const int lane = tid & 31;
    const int tok0 = b * SEQ;
    const int hoff = h * DHEAD;
    const int wq = wid * 16;
    const int koff16 = (lane >> 4) * 16;

    auto load_kv = [&](int jt) {
        const int j0 = jt * 64;
        const uint32_t base = sb + 2*TILE_B + (jt & 1) * 4*TILE_B;
        #pragma unroll
        for (int t = 0; t < 16; t++) {
            int idx = tid + t*128;                 // [0,2048)
            int op = idx >> 9, rem = idx & 511;
            int r = rem >> 3, g = rem & 7;
            const __nv_bfloat16* src =
                (op == 0 ? khi : op == 1 ? klo : op == 2 ? vhi : vlo)
                + (size_t)(tok0 + j0 + r)*DMODEL + hoff + g*8;
            cp_async16(base + op*TILE_B + r*144 + g*16, src);
        }
        CP_COMMIT();
    };

    // Q tiles + first K/V as group 0
    #pragma unroll
    for (int t = 0; t < 8; t++) {
        int idx = tid + t*128;
        int op = idx >> 9, rem = idx & 511;
        int r = rem >> 3, g = rem & 7;
        const __nv_bfloat16* src = (op ? qlo : qhi) + (size_t)(tok0 + i0 + r)*DMODEL + hoff + g*8;
        cp_async16(sb + op*TILE_B + r*144 + g*16, src);
    }
    load_kv(0);

    float m_i[2] = {-1e30f, -1e30f}, l_i[2] = {0.f, 0.f};
    float acc[8][4];
    #pragma unroll
    for (int n = 0; n < 8; n++)
        #pragma unroll
        for (int e = 0; e < 4; e++) acc[n][e] = 0.f;

    const float* skb = SK + ((size_t)bh << 20);
    const int row0 = i0 + wq + (lane >> 2);
    const int qc = (lane & 3) * 2;

    uint32_t ahq[4][4], alq[4][4];

    for (int jt = 0; jt < 16; jt++) {
        const int j0 = jt * 64;
        if (jt + 1 < 16) { load_kv(jt + 1); CP_WAIT(1); }
        else             { CP_WAIT(0); }
        __syncthreads();

        const uint32_t kvb = sb + 2*TILE_B + (jt & 1) * 4*TILE_B;

        if (jt == 0) {
            #pragma unroll
            for (int kt = 0; kt < 4; kt++) {
                uint32_t qa = sb + (wq + (lane & 15))*144 + kt*32 + koff16;
                ldm_x4(ahq[kt][0], ahq[kt][1], ahq[kt][2], ahq[kt][3], qa);
                ldm_x4(alq[kt][0], alq[kt][1], alq[kt][2], alq[kt][3], qa + TILE_B);
            }
        }

        // ---- S = Q K^T (bf16x3) ----
        float s[8][4];
        #pragma unroll
        for (int n = 0; n < 8; n++)
            #pragma unroll
            for (int e = 0; e < 4; e++) s[n][e] = 0.f;

        #pragma unroll
        for (int kt = 0; kt < 4; kt++) {
            uint32_t bh2[8][2], bl2[8][2];
            #pragma unroll
            for (int p = 0; p < 4; p++) {
                uint32_t r0, r1, r2, r3;
                uint32_t ba = kvb + (p*16 + (lane & 15))*144 + kt*32 + koff16;
                ldm_x4(r0, r1, r2, r3, ba);
                bh2[2*p][0] = r0; bh2[2*p][1] = r2; bh2[2*p+1][0] = r1; bh2[2*p+1][1] = r3;
                ldm_x4(r0, r1, r2, r3, ba + TILE_B);
                bl2[2*p][0] = r0; bl2[2*p][1] = r2; bl2[2*p+1][0] = r1; bl2[2*p+1][1] = r3;
            }
            #pragma unroll
            for (int n = 0; n < 8; n++) {
                mma_bf16(s[n][0], s[n][1], s[n][2], s[n][3],
                         ahq[kt][0], ahq[kt][1], ahq[kt][2], ahq[kt][3], bh2[n][0], bh2[n][1]);
                mma_bf16(s[n][0], s[n][1], s[n][2], s[n][3],
                         alq[kt][0], alq[kt][1], alq[kt][2], alq[kt][3], bh2[n][0], bh2[n][1]);
                mma_bf16(s[n][0], s[n][1], s[n][2], s[n][3],
                         ahq[kt][0], ahq[kt][1], ahq[kt][2], ahq[kt][3], bl2[n][0], bl2[n][1]);
            }
        }

        // ---- rel term + scale ----
        #pragma unroll
        for (int n = 0; n < 8; n++) {
            int jc = j0 + 8*n + qc;
            const float* p0 = skb + ((size_t)row0 << 10) + jc;
            const float* p1 = p0 + (8 << 10);
            if (jc     <= row0)     s[n][0] += p0[0];
            if (jc + 1 <= row0)     s[n][1] += p0[1];
            if (jc     <= row0 + 8) s[n][2] += p1[0];
            if (jc + 1 <= row0 + 8) s[n][3] += p1[1];
            #pragma unroll
            for (int e = 0; e < 4; e++) s[n][e] *= INV_SQRT_DH;
        }

        // ---- online softmax ----
        #pragma unroll
        for (int rr = 0; rr < 2; rr++) {
            float mx = -1e30f;
            #pragma unroll
            for (int n = 0; n < 8; n++) {
                mx = fmaxf(mx, s[n][2*rr]);
                mx = fmaxf(mx, s[n][2*rr + 1]);
            }
            mx = fmaxf(mx, __shfl_xor_sync(0xffffffffu, mx, 1));
            mx = fmaxf(mx, __shfl_xor_sync(0xffffffffu, mx, 2));
            float mn = fmaxf(m_i[rr], mx);
            float alpha = __expf(m_i[rr] - mn);
            float ps = 0.f;
            #pragma unroll
            for (int n = 0; n < 8; n++) {
                float p0 = __expf(s[n][2*rr]     - mn);
                float p1 = __expf(s[n][2*rr + 1] - mn);
                s[n][2*rr] = p0; s[n][2*rr + 1] = p1;
                ps += p0 + p1;
            }
            ps += __shfl_xor_sync(0xffffffffu, ps, 1);
            ps += __shfl_xor_sync(0xffffffffu, ps, 2);
            l_i[rr] = l_i[rr] * alpha + ps;
            m_i[rr] = mn;
            #pragma unroll
            for (int dn = 0; dn < 8; dn++) {
                acc[dn][2*rr]     *= alpha;
                acc[dn][2*rr + 1] *= alpha;
            }
        }

        // ---- pack P ----
        uint32_t ph[8][2], pl[8][2];
        #pragma unroll
        for (int n = 0; n < 8; n++) {
            split_pack(s[n][0], s[n][1], ph[n][0], pl[n][0]);
            split_pack(s[n][2], s[n][3], ph[n][1], pl[n][1]);
        }

        // ---- O += P V (V via ldmatrix.trans) ----
        const uint32_t vb = kvb + 2*TILE_B;
        #pragma unroll
        for (int kt = 0; kt < 4; kt++) {
            uint32_t ah0 = ph[2*kt][0], ah1 = ph[2*kt][1], ah2 = ph[2*kt+1][0], ah3 = ph[2*kt+1][1];
            uint32_t al0 = pl[2*kt][0], al1 = pl[2*kt][1], al2 = pl[2*kt+1][0], al3 = pl[2*kt+1][1];
            uint32_t vh2[8][2], vl2[8][2];
            #pragma unroll
            for (int p = 0; p < 4; p++) {
                uint32_t r0, r1, r2, r3;
                uint32_t va = vb + (kt*16 + (lane & 15))*144 + p*32 + koff16;
                ldm_x4t(r0, r1, r2, r3, va);
                vh2[2*p][0] = r0; vh2[2*p][1] = r1; vh2[2*p+1][0] = r2; vh2[2*p+1][1] = r3;
                ldm_x4t(r0, r1, r2, r3, va + TILE_B);
                vl2[2*p][0] = r0; vl2[2*p][1] = r1; vl2[2*p+1][0] = r2; vl2[2*p+1][1] = r3;
            }
            #pragma unroll
            for (int dn = 0; dn < 8; dn++) {
                mma_bf16(acc[dn][0], acc[dn][1], acc[dn][2], acc[dn][3],
                         ah0, ah1, ah2, ah3, vh2[dn][0], vh2[dn][1]);
                mma_bf16(acc[dn][0], acc[dn][1], acc[dn][2], acc[dn][3],
                         al0, al1, al2, al3, vh2[dn][0], vh2[dn][1]);
                mma_bf16(acc[dn][0], acc[dn][1], acc[dn][2], acc[dn][3],
                         ah0, ah1, ah2, ah3, vl2[dn][0], vl2[dn][1]);
            }
        }
        __syncthreads();
    }

    // normalize + split-store
    #pragma unroll
    for (int rr = 0; rr < 2; rr++) {
        float inv = 1.f / l_i[rr];
        int row = row0 + rr*8;
        #pragma unroll
        for (int dn = 0; dn < 8; dn++) {
            float o0 = acc[dn][2*rr] * inv, o1 = acc[dn][2*rr + 1] * inv;
            uint32_t hi, lo;
            split_pack(o0, o1, hi, lo);
            size_t oaddr = (size_t)(tok0 + row)*DMODEL + hoff + 8*dn + qc;
            *reinterpret_cast<uint32_t*>(Ohi + oaddr) = hi;
            *reinterpret_cast<uint32_t*>(Olo + oaddr) = lo;
        }
    }
}

// ---------------------------------------------------------------------------
// y = LayerNorm(a + b) * scale + bias; emits fp32 y and bf16 hi/lo split.
// ---------------------------------------------------------------------------
__global__ void add_ln_kernel(const float* __restrict__ a, const float* __restrict__ b,
                              const float* __restrict__ scale, const float* __restrict__ bias,
                              float* __restrict__ y,
                              __nv_bfloat16* __restrict__ yhi, __nv_bfloat16* __restrict__ ylo) {
    const int t = blockIdx.x;
    const int tid = threadIdx.x;       // 128
    const int d4 = tid * 4;
    const size_t base = (size_t)t*DMODEL + d4;
    float4 av = *reinterpret_cast<const float4*>(a + base);
    float4 bv = *reinterpret_cast<const float4*>(b + base);
    float x[4] = {av.x + bv.x, av.y + bv.y, av.z + bv.z, av.w + bv.w};
    float sum = x[0] + x[1] + x[2] + x[3];
    __shared__ float red[4];
    #pragma unroll
    for (int o = 16; o > 0; o >>= 1) sum += __shfl_xor_sync(0xffffffffu, sum, o);
    if ((tid & 31) == 0) red[tid >> 5] = sum;
    __syncthreads();
    sum = red[0] + red[1] + red[2] + red[3];
    const float mu = sum * (1.f/512.f);
    float vs = 0.f;
    #pragma unroll
    for (int i = 0; i < 4; i++) { float dd = x[i] - mu; vs = fmaf(dd, dd, vs); }
    #pragma unroll
    for (int o = 16; o > 0; o >>= 1) vs += __shfl_xor_sync(0xffffffffu, vs, o);
    __shared__ float red2[4];
    if ((tid & 31) == 0) red2[tid >> 5] = vs;
    __syncthreads();
    vs = red2[0] + red2[1] + red2[2] + red2[3];
    const float rstd = rsqrtf(vs * (1.f/512.f) + 1e-6f);
    float o[4];
    #pragma unroll
    for (int i = 0; i < 4; i++)
        o[i] = (x[i] - mu) * rstd * scale[d4 + i] + bias[d4 + i];
    *reinterpret_cast<float4*>(y + base) = make_float4(o[0], o[1], o[2], o[3]);
    uint32_t h0, l0, h1, l1;
    split_pack(o[0], o[1], h0, l0);
    split_pack(o[2], o[3], h1, l1);
    *reinterpret_cast<uint2*>(yhi + base) = make_uint2(h0, h1);
    *reinterpret_cast<uint2*>(ylo + base) = make_uint2(l0, l1);
}

// ---------------------------------------------------------------------------
// out[b,o] = tanh(h[b,0,:] . Wf[:,o] + bf[o])
// ---------------------------------------------------------------------------
__global__ void head_kernel(const float* __restrict__ Wf, const float* __restrict__ bf,
                            float* __restrict__ out) {
    const int w = threadIdx.x >> 5;
    const int lane = threadIdx.x & 31;
    const int b = w >> 1, o = w & 1;
    const float* hr = g_h + (size_t)b*SEQ*DMODEL;
    float sum = 0.f;
    #pragma unroll
    for (int d = lane; d < DMODEL; d += 32)
        sum = fmaf(hr[d], Wf[d*2 + o], sum);
    #pragma unroll
    for (int off = 16; off > 0; off >>= 1) sum += __shfl_xor_sync(0xffffffffu, sum, off);
    if (lane == 0) out[b*2 + o] = tanhf(sum + bf[o]);
}

// ---------------------------------------------------------------------------
// Launch
// ---------------------------------------------------------------------------
extern "C" void kernel_launch(void* const* d_in, const int* in_sizes, int n_in,
                              void* d_out, int out_size) {
    const int*   x    = (const int*)  d_in[0];
    const float* emb  = (const float*)d_in[1];
    const float* pos  = (const float*)d_in[2];
    const float* Wq   = (const float*)d_in[3];
    const float* bq   = (const float*)d_in[4];
    const float* Wk   = (const float*)d_in[5];
    const float* bk   = (const float*)d_in[6];
    const float* Wv   = (const float*)d_in[7];
    const float* bv   = (const float*)d_in[8];
    const float* Wo   = (const float*)d_in[9];
    const float* bo   = (const float*)d_in[10];
    const float* E    = (const float*)d_in[11];
    const float* W1   = (const float*)d_in[12];
    const float* b1   = (const float*)d_in[13];
    const float* W2   = (const float*)d_in[14];
    const float* b2   = (const float*)d_in[15];
    const float* ln1s = (const float*)d_in[16];
    const float* ln1b = (const float*)d_in[17];
    const float* ln2s = (const float*)d_in[18];
    const float* ln2b = (const float*)d_in[19];
    const float* Wf   = (const float*)d_in[20];
    const float* bf   = (const float*)d_in[21];
    float* out = (float*)d_out;

    float *h, *h1, *ffn, *sk;
    cudaGetSymbolAddress((void**)&h,   g_h);
    cudaGetSymbolAddress((void**)&h1,  g_h1);
    cudaGetSymbolAddress((void**)&ffn, g_ffn);
    cudaGetSymbolAddress((void**)&sk,  g_sk);

    __nv_bfloat16 *hhi, *hlo, *qh, *ql, *kh, *kl, *vh, *vl;
    __nv_bfloat16 *athi, *atlo, *h1hi, *h1lo, *mdhi, *mdlo, *ehi, *elo;
    __nv_bfloat16 *w4h, *w4l, *w1h, *w1l, *w2h, *w2l;
    cudaGetSymbolAddress((void**)&hhi,  g_h_hi);
    cudaGetSymbolAddress((void**)&hlo,  g_h_lo);
    cudaGetSymbolAddress((void**)&qh,   g_q_hi);
    cudaGetSymbolAddress((void**)&ql,   g_q_lo);
    cudaGetSymbolAddress((void**)&kh,   g_k_hi);
    cudaGetSymbolAddress((void**)&kl,   g_k_lo);
    cudaGetSymbolAddress((void**)&vh,   g_v_hi);
    cudaGetSymbolAddress((void**)&vl,   g_v_lo);
    cudaGetSymbolAddress((void**)&athi, g_attn_hi);
    cudaGetSymbolAddress((void**)&atlo, g_attn_lo);
    cudaGetSymbolAddress((void**)&h1hi, g_h1_hi);
    cudaGetSymbolAddress((void**)&h1lo, g_h1_lo);
    cudaGetSymbolAddress((void**)&mdhi, g_mid_hi);
    cudaGetSymbolAddress((void**)&mdlo, g_mid_lo);
    cudaGetSymbolAddress((void**)&ehi,  g_e_hi);
    cudaGetSymbolAddress((void**)&elo,  g_e_lo);
    cudaGetSymbolAddress((void**)&w4h, g_w4_hi);
    cudaGetSymbolAddress((void**)&w4l, g_w4_lo);
    cudaGetSymbolAddress((void**)&w1h, g_w1_hi);
    cudaGetSymbolAddress((void**)&w1l, g_w1_lo);
    cudaGetSymbolAddress((void**)&w2h, g_w2_hi);
    cudaGetSymbolAddress((void**)&w2l, g_w2_lo);

    cudaFuncSetAttribute(attention2_kernel, cudaFuncAttributeMaxDynamicSharedMemorySize, AT2_SMEM);
    cudaFuncSetAttribute(qe_skew2_kernel,   cudaFuncAttributeMaxDynamicSharedMemorySize, QE2_SMEM);
    cudaFuncSetAttribute((const void*)mma_gemm_kernel<0,false>, cudaFuncAttributeMaxDynamicSharedMemorySize, MMA_SMEM);
    cudaFuncSetAttribute((const void*)mma_gemm_kernel<1,true>,  cudaFuncAttributeMaxDynamicSharedMemorySize, MMA_SMEM);
    cudaFuncSetAttribute((const void*)mma_gemm_qkv_kernel,      cudaFuncAttributeMaxDynamicSharedMemorySize, MMA_SMEM);

    const size_t SZ = (size_t)DMODEL * DMODEL;      // 262144

    wconv_t_kernel<<<dim3(16,16,NLAYER), 256>>>(Wq, w4h + 0*SZ, w4l + 0*SZ, DMODEL, DMODEL, SZ, 4*SZ);
    wconv_t_kernel<<<dim3(16,16,NLAYER), 256>>>(Wk, w4h + 1*SZ, w4l + 1*SZ, DMODEL, DMODEL, SZ, 4*SZ);
    wconv_t_kernel<<<dim3(16,16,NLAYER), 256>>>(Wv, w4h + 2*SZ, w4l + 2*SZ, DMODEL, DMODEL, SZ, 4*SZ);
    wconv_t_kernel<<<dim3(16,16,NLAYER), 256>>>(Wo, w4h + 3*SZ, w4l + 3*SZ, DMODEL, DMODEL, SZ, 4*SZ);
    wconv_t_kernel<<<dim3(64,16,NLAYER), 256>>>(W1, w1h, w1l, DMODEL, DINNER,
                                                (size_t)DMODEL*DINNER, (size_t)DINNER*DMODEL);
    wconv_t_kernel<<<dim3(16,64,NLAYER), 256>>>(W2, w2h, w2l, DINNER, DMODEL,
                                                (size_t)DINNER*DMODEL, (size_t)DMODEL*DINNER);
    econv_kernel<<<NLAYER*SEQ*DHEAD/4/256, 256>>>(E);

    embed_kernel<<<NTOK*DMODEL/4/256, 256>>>(x, emb, pos);

    for (int l = 0; l < NLAYER; l++) {
        const __nv_bfloat16* l4h = w4h + (size_t)l*4*SZ;
        const __nv_bfloat16* l4l = w4l + (size_t)l*4*SZ;

        mma_gemm_qkv_kernel<<<dim3(8,32,3), 128, MMA_SMEM>>>(hhi, hlo, l4h, l4l,
            bq + l*DMODEL, bk + l*DMODEL, bv + l*DMODEL, qh, ql, kh, kl, vh, vl);

        qe_skew2_kernel<<<dim3(16,32), 128, QE2_SMEM>>>(qh, ql,
            ehi + (size_t)l*SEQ*DHEAD, elo + (size_t)l*SEQ*DHEAD, sk);
        attention2_kernel<<<dim3(16,32), 128, AT2_SMEM>>>(qh, ql, kh, kl, vh, vl, sk, athi, atlo);

        mma_gemm_kernel<0,false><<<dim3(8,32), 128, MMA_SMEM>>>(athi, atlo, l4h + 3*SZ, l4l + 3*SZ,
            bo + l*DMODEL, ffn, nullptr, nullptr, NTOK, DMODEL, DMODEL);
        add_ln_kernel<<<NTOK, 128>>>(ffn, h, ln1s + l*DMODEL, ln1b + l*DMODEL, h1, h1hi, h1lo);

        mma_gemm_kernel<1,true><<<dim3(32,32), 128, MMA_SMEM>>>(h1hi, h1lo,
            w1h + (size_t)l*DINNER*DMODEL, w1l + (size_t)l*DINNER*DMODEL,
            b1 + l*DINNER, nullptr, mdhi, mdlo, NTOK, DINNER, DMODEL);

        mma_gemm_kernel<0,false><<<dim3(8,32), 128, MMA_SMEM>>>(mdhi, mdlo,
            w2h + (size_t)l*DMODEL*DINNER, w2l + (size_t)l*DMODEL*DINNER,
            b2 + l*DMODEL, ffn, nullptr, nullptr, NTOK, DMODEL, DINNER);
        add_ln_kernel<<<NTOK, 128>>>(h1, ffn, ln2s + l*DMODEL, ln2b + l*DMODEL, h, hhi, hlo);
    }

    head_kernel<<<1, 256>>>(Wf, bf, out);
}